// round 1
// baseline (speedup 1.0000x reference)
#include <cuda_runtime.h>
#include <cuda_bf16.h>

// ---------------------------------------------------------------------------
// MultilayerDeformableC3D: 3x conv3d(256->256,3^3)+relu, conv3d(256->81) offsets,
// deformable conv3d(256->256). All convs lowered to GEMM with K = 256*27 = 6912.
// fp32 SIMT baseline (FFMA-bound ~36 TF/s ceiling on sm_100a).
// ---------------------------------------------------------------------------

#define T_   8
#define H_   24
#define W_   24
#define N_   4608            // T*H*W
#define CIN_ 256
#define KV_  27
#define KD_  6912            // CIN_*KV_

// Scratch (device-global, no allocations allowed)
__device__ float g_col[(size_t)KD_ * N_];   // 127 MB im2col / deform-col buffer
__device__ float g_h1[(size_t)CIN_ * N_];
__device__ float g_h2[(size_t)CIN_ * N_];
__device__ float g_off[(size_t)81 * N_];

// ---------------------------------------------------------------------------
// im2col: col[(ci*27+k)][n] = src[ci][t+dt][h+dh][w+dw] with zero padding
// grid: (ceil(N/256), KD_), block 256
// ---------------------------------------------------------------------------
__global__ void im2col_k(const float* __restrict__ src, float* __restrict__ col)
{
    int n = blockIdx.x * blockDim.x + threadIdx.x;
    if (n >= N_) return;
    int Kidx = blockIdx.y;
    int ci = Kidx / KV_;
    int k  = Kidx % KV_;
    int dt = k / 9 - 1;
    int dh = (k / 3) % 3 - 1;
    int dw = k % 3 - 1;

    int t = n / (H_ * W_);
    int hw = n - t * (H_ * W_);
    int h = hw / W_;
    int w = hw - h * W_;

    int tt = t + dt, hh = h + dh, ww = w + dw;
    float v = 0.f;
    if ((unsigned)tt < (unsigned)T_ && (unsigned)hh < (unsigned)H_ && (unsigned)ww < (unsigned)W_)
        v = src[(size_t)ci * N_ + (tt * H_ + hh) * W_ + ww];
    col[(size_t)Kidx * N_ + n] = v;
}

// ---------------------------------------------------------------------------
// deform_col: col[(ci*27+k)][n] = trilinear-interp of x at base+koff+offset,
// zero outside bounds (weights masked, indices clamped — matches reference).
// grid: (ceil(N/128), 27), block 128. Each thread loops over all 256 ci.
// ---------------------------------------------------------------------------
__global__ void deform_col_k(const float* __restrict__ x,
                             const float* __restrict__ off,
                             float* __restrict__ col)
{
    int n = blockIdx.x * blockDim.x + threadIdx.x;
    if (n >= N_) return;
    int k = blockIdx.y;  // 0..26

    int t = n / (H_ * W_);
    int hw = n - t * (H_ * W_);
    int h = hw / W_;
    int w = hw - h * W_;

    int dt = k / 9 - 1;
    int dh = (k / 3) % 3 - 1;
    int dw = k % 3 - 1;

    float pt = (float)(t + dt) + off[(size_t)(k * 3 + 0) * N_ + n];
    float ph = (float)(h + dh) + off[(size_t)(k * 3 + 1) * N_ + n];
    float pw = (float)(w + dw) + off[(size_t)(k * 3 + 2) * N_ + n];

    float ft = floorf(pt), fh = floorf(ph), fw = floorf(pw);
    float at = pt - ft, ah = ph - fh, aw = pw - fw;
    int it = (int)ft, ih = (int)fh, iw = (int)fw;

    int   idx8[8];
    float wt8[8];
#pragma unroll
    for (int c = 0; c < 8; c++) {
        int ddt = (c >> 2) & 1, ddh = (c >> 1) & 1, ddw = c & 1;
        int tt = it + ddt, hh = ih + ddh, ww = iw + ddw;
        bool valid = (tt >= 0 && tt < T_ && hh >= 0 && hh < H_ && ww >= 0 && ww < W_);
        int tc = min(max(tt, 0), T_ - 1);
        int hc = min(max(hh, 0), H_ - 1);
        int wc = min(max(ww, 0), W_ - 1);
        float wg = (ddt ? at : 1.f - at) * (ddh ? ah : 1.f - ah) * (ddw ? aw : 1.f - aw);
        wt8[c]  = valid ? wg : 0.f;
        idx8[c] = (tc * H_ + hc) * W_ + wc;
    }

    for (int ci = 0; ci < CIN_; ci++) {
        const float* xb = x + (size_t)ci * N_;
        float v = 0.f;
#pragma unroll
        for (int c = 0; c < 8; c++) v += wt8[c] * __ldg(&xb[idx8[c]]);
        col[(size_t)(ci * KV_ + k) * N_ + n] = v;
    }
}

// ---------------------------------------------------------------------------
// GEMM: C[M][N_] = A[M][KD_] * Bm[KD_][N_] + bias  (optional ReLU)
// BM=64, BN=48, BK=16, 128 threads, per-thread 4m x 6n register tile.
// Register-prefetch double buffering to hide gmem latency under FFMA.
// grid: (N_/48 = 96, ceil(M/64))
// ---------------------------------------------------------------------------
template <bool RELU>
__global__ void __launch_bounds__(128)
gemm_k(const float* __restrict__ A, const float* __restrict__ Bm,
       const float* __restrict__ bias, float* __restrict__ C, int M)
{
    __shared__ float As[16][68];   // [k][m], padded: conflict-free + 16B aligned rows
    __shared__ float Bs[16][48];   // [k][n]

    const int tid = threadIdx.x;
    const int m0 = blockIdx.y * 64;
    const int n0 = blockIdx.x * 48;

    // A-tile load mapping: 256 float4 items (64 m x 4 vec), 2 per thread
    const int am  = tid >> 2;          // 0..31 (second load: +32)
    const int ak  = (tid & 3) * 4;     // 0,4,8,12
    const bool av0 = (m0 + am)      < M;
    const bool av1 = (m0 + am + 32) < M;

    // B-tile load mapping: 384 float2 items, 3 per thread
    int br[3], bc[3];
#pragma unroll
    for (int j = 0; j < 3; j++) {
        int p = tid + j * 128;
        br[j] = p / 24;
        bc[j] = (p - br[j] * 24) * 2;
    }

    const int ty = tid >> 3;  // 0..15 -> m sub-tile (4 rows)
    const int tx = tid & 7;   // 0..7  -> n sub-tile (6 cols)

    float acc[4][6];
#pragma unroll
    for (int i = 0; i < 4; i++)
#pragma unroll
        for (int j = 0; j < 6; j++) acc[i][j] = 0.f;

    float4 af0, af1;
    float2 bf[3];

    // prologue: load k-tile 0
    {
        const float zero4[4] = {0, 0, 0, 0};
        af0 = av0 ? *(const float4*)&A[(size_t)(m0 + am) * KD_ + ak]
                  : *(const float4*)zero4;
        af1 = av1 ? *(const float4*)&A[(size_t)(m0 + am + 32) * KD_ + ak]
                  : *(const float4*)zero4;
#pragma unroll
        for (int j = 0; j < 3; j++)
            bf[j] = *(const float2*)&Bm[(size_t)br[j] * N_ + n0 + bc[j]];
    }

    for (int k0 = 0; k0 < KD_; k0 += 16) {
        // stage registers -> smem
#pragma unroll
        for (int j = 0; j < 4; j++) {
            As[ak + j][am]      = (&af0.x)[j];
            As[ak + j][am + 32] = (&af1.x)[j];
        }
#pragma unroll
        for (int j = 0; j < 3; j++) {
            Bs[br[j]][bc[j]]     = bf[j].x;
            Bs[br[j]][bc[j] + 1] = bf[j].y;
        }
        __syncthreads();

        // prefetch next k-tile (latency hidden under the 16x24 FMA block below)
        int kn = k0 + 16;
        if (kn < KD_) {
            const float zero4[4] = {0, 0, 0, 0};
            af0 = av0 ? *(const float4*)&A[(size_t)(m0 + am) * KD_ + kn + ak]
                      : *(const float4*)zero4;
            af1 = av1 ? *(const float4*)&A[(size_t)(m0 + am + 32) * KD_ + kn + ak]
                      : *(const float4*)zero4;
#pragma unroll
            for (int j = 0; j < 3; j++)
                bf[j] = *(const float2*)&Bm[(size_t)(kn + br[j]) * N_ + n0 + bc[j]];
        }

        // compute
#pragma unroll
        for (int kk = 0; kk < 16; kk++) {
            float4 avv = *(const float4*)&As[kk][ty * 4];
            float bvv[6];
#pragma unroll
            for (int j = 0; j < 6; j++) bvv[j] = Bs[kk][tx * 6 + j];
#pragma unroll
            for (int i = 0; i < 4; i++)
#pragma unroll
                for (int j = 0; j < 6; j++)
                    acc[i][j] += (&avv.x)[i] * bvv[j];
        }
        __syncthreads();
    }

    // epilogue
#pragma unroll
    for (int i = 0; i < 4; i++) {
        int m = m0 + ty * 4 + i;
        if (m < M) {
            float bv = bias[m];
#pragma unroll
            for (int j = 0; j < 6; j++) {
                float v = acc[i][j] + bv;
                if (RELU) v = fmaxf(v, 0.f);
                C[(size_t)m * N_ + n0 + tx * 6 + j] = v;
            }
        }
    }
}

// ---------------------------------------------------------------------------
extern "C" void kernel_launch(void* const* d_in, const int* in_sizes, int n_in,
                              void* d_out, int out_size)
{
    const float* x     = (const float*)d_in[0];
    const float* l1_w  = (const float*)d_in[1];
    const float* l1_b  = (const float*)d_in[2];
    const float* l2_w  = (const float*)d_in[3];
    const float* l2_b  = (const float*)d_in[4];
    const float* l3_w  = (const float*)d_in[5];
    const float* l3_b  = (const float*)d_in[6];
    const float* def_w = (const float*)d_in[7];
    const float* def_b = (const float*)d_in[8];
    const float* c3d_w = (const float*)d_in[9];
    const float* c3d_b = (const float*)d_in[10];
    float* out = (float*)d_out;

    float *col, *h1, *h2, *off;
    cudaGetSymbolAddress((void**)&col, g_col);
    cudaGetSymbolAddress((void**)&h1,  g_h1);
    cudaGetSymbolAddress((void**)&h2,  g_h2);
    cudaGetSymbolAddress((void**)&off, g_off);

    dim3 colGrid((N_ + 255) / 256, KD_);
    dim3 gemmGrid256(N_ / 48, 4);  // M=256
    dim3 gemmGrid81(N_ / 48, 2);   // M=81 (guarded)
    dim3 defGrid((N_ + 127) / 128, KV_);

    // layer 1
    im2col_k<<<colGrid, 256>>>(x, col);
    gemm_k<true><<<gemmGrid256, 128>>>(l1_w, col, l1_b, h1, 256);
    // layer 2
    im2col_k<<<colGrid, 256>>>(h1, col);
    gemm_k<true><<<gemmGrid256, 128>>>(l2_w, col, l2_b, h2, 256);
    // layer 3
    im2col_k<<<colGrid, 256>>>(h2, col);
    gemm_k<true><<<gemmGrid256, 128>>>(l3_w, col, l3_b, h1, 256);
    // offsets conv (no relu)
    im2col_k<<<colGrid, 256>>>(h1, col);
    gemm_k<false><<<gemmGrid81, 128>>>(def_w, col, def_b, off, 81);
    // deformable gather + final GEMM
    deform_col_k<<<defGrid, 128>>>(x, off, col);
    gemm_k<false><<<gemmGrid256, 128>>>(c3d_w, col, c3d_b, out, 256);
}

// round 3
// speedup vs baseline: 1.0592x; 1.0592x over previous
#include <cuda_runtime.h>
#include <cuda_bf16.h>

// ---------------------------------------------------------------------------
// MultilayerDeformableC3D — implicit-im2col fp32 GEMM version.
// conv layers: C[M][4608] = W[M][6912] * im2col(src)[6912][4608], fused gather.
// deform layer: materialize deform-col, then plain GEMM.
// ---------------------------------------------------------------------------

#define T_   8
#define H_   24
#define W_   24
#define N_   4608            // T*H*W
#define CIN_ 256
#define KV_  27
#define KD_  6912            // CIN_*KV_

#define BM 64
#define BN 64
#define BK 16

// Scratch (device-global; no allocations allowed)
__device__ float g_col[(size_t)KD_ * N_];   // deform-col buffer (127 MB)
__device__ float g_h1[(size_t)CIN_ * N_];
__device__ float g_h2[(size_t)CIN_ * N_];
__device__ float g_off[(size_t)81 * N_];

// ---------------------------------------------------------------------------
// deform_col: col[(ci*27+k)][n] = trilinear interp of x at base+koff+offset.
// grid: (N_/128, 27), block 128. Each thread loops over all 256 ci.
// ---------------------------------------------------------------------------
__global__ void deform_col_k(const float* __restrict__ x,
                             const float* __restrict__ off,
                             float* __restrict__ col)
{
    int n = blockIdx.x * blockDim.x + threadIdx.x;
    if (n >= N_) return;
    int k = blockIdx.y;  // 0..26

    int t = n / (H_ * W_);
    int hw = n - t * (H_ * W_);
    int h = hw / W_;
    int w = hw - h * W_;

    int dt = k / 9 - 1;
    int dh = (k / 3) % 3 - 1;
    int dw = k % 3 - 1;

    float pt = (float)(t + dt) + off[(size_t)(k * 3 + 0) * N_ + n];
    float ph = (float)(h + dh) + off[(size_t)(k * 3 + 1) * N_ + n];
    float pw = (float)(w + dw) + off[(size_t)(k * 3 + 2) * N_ + n];

    float ft = floorf(pt), fh = floorf(ph), fw = floorf(pw);
    float at = pt - ft, ah = ph - fh, aw = pw - fw;
    int it = (int)ft, ih = (int)fh, iw = (int)fw;

    int   idx8[8];
    float wt8[8];
#pragma unroll
    for (int c = 0; c < 8; c++) {
        int ddt = (c >> 2) & 1, ddh = (c >> 1) & 1, ddw = c & 1;
        int tt = it + ddt, hh = ih + ddh, ww = iw + ddw;
        bool valid = (tt >= 0 && tt < T_ && hh >= 0 && hh < H_ && ww >= 0 && ww < W_);
        int tc = min(max(tt, 0), T_ - 1);
        int hc = min(max(hh, 0), H_ - 1);
        int wc = min(max(ww, 0), W_ - 1);
        float wg = (ddt ? at : 1.f - at) * (ddh ? ah : 1.f - ah) * (ddw ? aw : 1.f - aw);
        wt8[c]  = valid ? wg : 0.f;
        idx8[c] = (tc * H_ + hc) * W_ + wc;
    }

    for (int ci = 0; ci < CIN_; ci++) {
        const float* xb = x + (size_t)ci * N_;
        float v = 0.f;
#pragma unroll
        for (int c = 0; c < 8; c++) v += wt8[c] * __ldg(&xb[idx8[c]]);
        col[(size_t)(ci * KV_ + k) * N_ + n] = v;
    }
}

// ---------------------------------------------------------------------------
// GEMM: C[M][N_] = A[M][KD_] * B[KD_][N_] + bias (optional ReLU).
// FUSED: B is a feature map [CIN_][N_]; rows kd=ci*27+k27 are gathered
//        (implicit im2col with zero padding).
// BM=BN=64, BK=16, 128 threads, per-thread 8m x 4n register tile.
// Register-prefetch double buffering. grid: (N_/64 = 72, ceil(M/64)).
// ---------------------------------------------------------------------------
template <bool RELU, bool FUSED>
__global__ void __launch_bounds__(128)
gemm2_k(const float* __restrict__ A, const float* __restrict__ B,
        const float* __restrict__ bias, float* __restrict__ C, int M)
{
    __shared__ float As[BK][BM + 4];   // [k][m], row stride 68 (272B, 16B mult)
    __shared__ float Bs[BK][BN + 4];   // [k][n]

    const int tid = threadIdx.x;
    const int m0 = blockIdx.y * BM;
    const int n0 = blockIdx.x * BN;

    // ---- A-tile load map: 64m x 16k, 2 float4 per thread (transpose to smem)
    const int am = tid >> 2;          // 0..31 (and +32)
    const int ak = (tid & 3) * 4;     // 0,4,8,12
    const bool av0 = (m0 + am)      < M;
    const bool av1 = (m0 + am + 32) < M;
    const float* Arow0 = A + (size_t)(m0 + am) * KD_ + ak;
    const float* Arow1 = A + (size_t)(m0 + am + 32) * KD_ + ak;

    // ---- B-tile load map (column strip): column bc, 8 k-rows from br0
    const int bc  = tid & 63;         // 0..63 -> n column (coalesced lanes)
    const int br0 = (tid >> 6) * 8;   // 0 or 8
    const int n   = n0 + bc;
    int nt = 0, nh = 0, nw = 0;
    if (FUSED) {                      // per-thread constant decomposition
        nt = n / (H_ * W_);
        int rem = n - nt * (H_ * W_);
        nh = rem / W_;
        nw = rem - nh * W_;
    }

    // ---- compute map: 8m x 4n per thread
    const int ty = tid >> 4;          // 0..7  -> m group of 8
    const int tx = tid & 15;          // 0..15 -> n group of 4

    float acc[8][4];
#pragma unroll
    for (int i = 0; i < 8; i++)
#pragma unroll
        for (int j = 0; j < 4; j++) acc[i][j] = 0.f;

    float4 af0, af1;
    float  bf[8];

    // ---- fetch helpers
    auto fetchA = [&](int k0) {
        const float4 z = {0.f, 0.f, 0.f, 0.f};
        af0 = av0 ? *(const float4*)(Arow0 + k0) : z;
        af1 = av1 ? *(const float4*)(Arow1 + k0) : z;
    };
    auto fetchB = [&](int k0) {
#pragma unroll
        for (int r = 0; r < 8; r++) {
            int kd = k0 + br0 + r;
            if (FUSED) {
                int ci  = kd / KV_;
                int k27 = kd - ci * KV_;
                int kt  = k27 / 9;
                int r9  = k27 - kt * 9;
                int kh  = r9 / 3;
                int kw  = r9 - kh * 3;
                int tt = nt + kt - 1, hh = nh + kh - 1, ww = nw + kw - 1;
                float v = 0.f;
                if ((unsigned)tt < (unsigned)T_ && (unsigned)hh < (unsigned)H_ &&
                    (unsigned)ww < (unsigned)W_)
                    v = __ldg(B + (size_t)ci * N_ + (tt * H_ + hh) * W_ + ww);
                bf[r] = v;
            } else {
                bf[r] = __ldg(B + (size_t)kd * N_ + n);
            }
        }
    };

    fetchA(0);
    fetchB(0);

    for (int k0 = 0; k0 < KD_; k0 += BK) {
        // stage registers -> smem
#pragma unroll
        for (int j = 0; j < 4; j++) {
            As[ak + j][am]      = (&af0.x)[j];
            As[ak + j][am + 32] = (&af1.x)[j];
        }
#pragma unroll
        for (int r = 0; r < 8; r++) Bs[br0 + r][bc] = bf[r];
        __syncthreads();

        // prefetch next tile (hidden under FFMA block)
        if (k0 + BK < KD_) { fetchA(k0 + BK); fetchB(k0 + BK); }

        // compute: 16 x (32 FFMA : 3 LDS.128)
#pragma unroll
        for (int kk = 0; kk < BK; kk++) {
            float4 a0 = *(const float4*)&As[kk][ty * 8];
            float4 a1 = *(const float4*)&As[kk][ty * 8 + 4];
            float4 b0 = *(const float4*)&Bs[kk][tx * 4];
#pragma unroll
            for (int i = 0; i < 4; i++) {
#pragma unroll
                for (int j = 0; j < 4; j++) {
                    acc[i][j]     += (&a0.x)[i] * (&b0.x)[j];
                    acc[i + 4][j] += (&a1.x)[i] * (&b0.x)[j];
                }
            }
        }
        __syncthreads();
    }

    // ---- epilogue: bias (+ReLU), vectorized stores
#pragma unroll
    for (int i = 0; i < 8; i++) {
        int m = m0 + ty * 8 + i;
        if (m < M) {
            float bv = bias[m];
            float4 v;
#pragma unroll
            for (int j = 0; j < 4; j++) {
                float u = acc[i][j] + bv;
                if (RELU) u = fmaxf(u, 0.f);
                (&v.x)[j] = u;
            }
            *(float4*)&C[(size_t)m * N_ + n0 + tx * 4] = v;
        }
    }
}

// ---------------------------------------------------------------------------
extern "C" void kernel_launch(void* const* d_in, const int* in_sizes, int n_in,
                              void* d_out, int out_size)
{
    const float* x     = (const float*)d_in[0];
    const float* l1_w  = (const float*)d_in[1];
    const float* l1_b  = (const float*)d_in[2];
    const float* l2_w  = (const float*)d_in[3];
    const float* l2_b  = (const float*)d_in[4];
    const float* l3_w  = (const float*)d_in[5];
    const float* l3_b  = (const float*)d_in[6];
    const float* def_w = (const float*)d_in[7];
    const float* def_b = (const float*)d_in[8];
    const float* c3d_w = (const float*)d_in[9];
    const float* c3d_b = (const float*)d_in[10];
    float* out = (float*)d_out;

    float *col, *h1, *h2, *off;
    cudaGetSymbolAddress((void**)&col, g_col);
    cudaGetSymbolAddress((void**)&h1,  g_h1);
    cudaGetSymbolAddress((void**)&h2,  g_h2);
    cudaGetSymbolAddress((void**)&off, g_off);

    dim3 g256(N_ / BN, (256 + BM - 1) / BM);  // (72, 4)
    dim3 g81 (N_ / BN, (81  + BM - 1) / BM);  // (72, 2)
    dim3 defGrid(N_ / 128, KV_);

    // 3 conv layers (implicit im2col, fused ReLU)
    gemm2_k<true,  true ><<<g256, 128>>>(l1_w, x,  l1_b, h1, 256);
    gemm2_k<true,  true ><<<g256, 128>>>(l2_w, h1, l2_b, h2, 256);
    gemm2_k<true,  true ><<<g256, 128>>>(l3_w, h2, l3_b, h1, 256);
    // offsets conv (no relu)
    gemm2_k<false, true ><<<g81, 128>>>(def_w, h1, def_b, off, 81);
    // deformable gather + final plain GEMM
    deform_col_k<<<defGrid, 128>>>(x, off, col);
    gemm2_k<false, false><<<g256, 128>>>(c3d_w, col, c3d_b, out, 256);
}

// round 6
// speedup vs baseline: 1.2797x; 1.2081x over previous
#include <cuda_runtime.h>
#include <cuda_bf16.h>
#include <cstdint>

// ---------------------------------------------------------------------------
// MultilayerDeformableC3D — mma.sync TF32 (3xTF32 split) implicit-im2col GEMM.
// (tcgen05 unavailable: harness compiles for base sm_100 target.)
// ---------------------------------------------------------------------------

#define T_   8
#define H_   24
#define W_   24
#define N_   4608
#define CIN_ 256
#define KV_  27
#define KD_  6912

#define BM 128
#define BN 64
#define BK 16
#define NC (KD_ / BK)   // 432

// scratch
__device__ float g_col[(size_t)KD_ * N_];
__device__ float g_h1[(size_t)CIN_ * N_];
__device__ float g_h2[(size_t)CIN_ * N_];
__device__ float g_off[(size_t)81 * N_];
__device__ float g_xT[(size_t)N_ * CIN_];

__device__ __forceinline__ uint32_t tf32r(float v) {
    uint32_t r;
    asm("cvt.rna.tf32.f32 %0, %1;" : "=r"(r) : "f"(v));
    return r;
}
__device__ __forceinline__ void mma8(float c[4],
                                     uint32_t a0, uint32_t a1, uint32_t a2, uint32_t a3,
                                     uint32_t b0, uint32_t b1) {
    asm volatile(
        "mma.sync.aligned.m16n8k8.row.col.f32.tf32.tf32.f32 "
        "{%0,%1,%2,%3}, {%4,%5,%6,%7}, {%8,%9}, {%0,%1,%2,%3};"
        : "+f"(c[0]), "+f"(c[1]), "+f"(c[2]), "+f"(c[3])
        : "r"(a0), "r"(a1), "r"(a2), "r"(a3), "r"(b0), "r"(b1));
}

// ---------------------------------------------------------------------------
// GEMM: C[Mtot][N_] = A[Mtot][KD_] * B[KD_][N_] + bias (optional ReLU)
// FUSED: B rows gathered implicitly (im2col) from feature map [CIN_][N_]
// 256 thr = 8 warps (4m x 2n), warp tile 32x32, 3xTF32 split per fragment.
// ---------------------------------------------------------------------------
template <bool RELU, bool FUSED>
__global__ void __launch_bounds__(256)
gemm_mma(const float* __restrict__ A, const float* __restrict__ Bsrc,
         const float* __restrict__ bias, float* __restrict__ C, int Mtot)
{
    __shared__ float As[2][BM][20];   // [m][k], stride 20 floats (80B, 16B mult)
    __shared__ float Bs[2][BK][68];   // [k][n]
    __shared__ int   tbl[KV_];

    const int tid  = threadIdx.x;
    const int wid  = tid >> 5;
    const int lane = tid & 31;
    const int q = lane >> 2;          // 0..7
    const int r = lane & 3;           // 0..3
    const int m0 = blockIdx.y * BM;
    const int n0 = blockIdx.x * BN;
    const int m0w = (wid & 3) * 32;   // warp m offset
    const int n0w = (wid >> 2) * 32;  // warp n offset

    if (tid < KV_) {
        int dt = tid / 9 - 1, dh = (tid / 3) % 3 - 1, dw = tid % 3 - 1;
        tbl[tid] = dt * (H_ * W_) + dh * W_ + dw;
    }

    // ---- A (weights) load map: 2 float4 per thread per chunk
    const int arow = tid >> 2;        // 0..63 (and +64)
    const int akq  = tid & 3;         // float4 index within 16-k row
    const bool av0 = (m0 + arow)      < Mtot;
    const bool av1 = (m0 + arow + 64) < Mtot;
    const float* ap0 = A + (size_t)(m0 + arow) * KD_ + akq * 4;
    const float* ap1 = A + (size_t)(m0 + arow + 64) * KD_ + akq * 4;

    // ---- B load map: column bn, 4 k-rows (rg*4..rg*4+3)
    const int bn = tid & 63;
    const int rg = tid >> 6;
    const int n  = n0 + bn;
    uint32_t vmask = 0;
    int ci4[4], k274[4];
    if (FUSED) {
        int nt_ = n / (H_ * W_);
        int rem = n - nt_ * (H_ * W_);
        int nh_ = rem / W_;
        int nw_ = rem - nh_ * W_;
        for (int k = 0; k < KV_; k++) {
            int dt = k / 9 - 1, dh = (k / 3) % 3 - 1, dw = k % 3 - 1;
            int tt = nt_ + dt, hh = nh_ + dh, ww = nw_ + dw;
            if ((unsigned)tt < (unsigned)T_ && (unsigned)hh < (unsigned)H_ &&
                (unsigned)ww < (unsigned)W_)
                vmask |= 1u << k;
        }
#pragma unroll
        for (int j = 0; j < 4; j++) {
            int kd0 = rg * 4 + j;          // < 16 < 27
            ci4[j]  = 0;
            k274[j] = kd0;
        }
    }
    __syncthreads();   // tbl visible before first fused gather

    float4 ra0, ra1;
    float  rb[4];

    auto ldgA = [&](int k0) {
        const float4 z = {0.f, 0.f, 0.f, 0.f};
        ra0 = av0 ? __ldg((const float4*)(ap0 + k0)) : z;
        ra1 = av1 ? __ldg((const float4*)(ap1 + k0)) : z;
    };
    auto ldgB = [&](int k0) {
        if (FUSED) {
#pragma unroll
            for (int j = 0; j < 4; j++) {
                int k27 = k274[j], ci = ci4[j];
                float v = 0.f;
                if ((vmask >> k27) & 1u)
                    v = __ldg(Bsrc + (size_t)ci * N_ + n + tbl[k27]);
                rb[j] = v;
                k27 += BK;                     // advance by one chunk
                if (k27 >= KV_) { k27 -= KV_; ci++; }
                k274[j] = k27; ci4[j] = ci;
            }
        } else {
#pragma unroll
            for (int j = 0; j < 4; j++)
                rb[j] = __ldg(Bsrc + (size_t)(k0 + rg * 4 + j) * N_ + n);
        }
    };
    auto sts = [&](int p) {
        *(float4*)&As[p][arow][akq * 4]      = ra0;
        *(float4*)&As[p][arow + 64][akq * 4] = ra1;
#pragma unroll
        for (int j = 0; j < 4; j++) Bs[p][rg * 4 + j][bn] = rb[j];
    };

    float acc[2][4][4];
#pragma unroll
    for (int mt = 0; mt < 2; mt++)
#pragma unroll
        for (int nt = 0; nt < 4; nt++)
#pragma unroll
            for (int j = 0; j < 4; j++) acc[mt][nt][j] = 0.f;

    // prologue
    ldgA(0); ldgB(0);
    sts(0);
    __syncthreads();

    for (int c = 0; c < NC; c++) {
        const int p = c & 1;
        if (c + 1 < NC) { ldgA((c + 1) * BK); ldgB((c + 1) * BK); }

#pragma unroll
        for (int ks = 0; ks < 2; ks++) {
            const int kb = ks * 8;
            // A fragments (hi/lo split)
            uint32_t ahi[2][4], alo[2][4];
#pragma unroll
            for (int mt = 0; mt < 2; mt++) {
                float v0 = As[p][m0w + mt * 16 + q][kb + r];
                float v1 = As[p][m0w + mt * 16 + q + 8][kb + r];
                float v2 = As[p][m0w + mt * 16 + q][kb + r + 4];
                float v3 = As[p][m0w + mt * 16 + q + 8][kb + r + 4];
                ahi[mt][0] = tf32r(v0); alo[mt][0] = __float_as_uint(v0 - __uint_as_float(ahi[mt][0]));
                ahi[mt][1] = tf32r(v1); alo[mt][1] = __float_as_uint(v1 - __uint_as_float(ahi[mt][1]));
                ahi[mt][2] = tf32r(v2); alo[mt][2] = __float_as_uint(v2 - __uint_as_float(ahi[mt][2]));
                ahi[mt][3] = tf32r(v3); alo[mt][3] = __float_as_uint(v3 - __uint_as_float(ahi[mt][3]));
            }
            // B fragments (hi/lo split)
            uint32_t bhi[4][2], blo[4][2];
#pragma unroll
            for (int nt = 0; nt < 4; nt++) {
                float u0 = Bs[p][kb + r][n0w + nt * 8 + q];
                float u1 = Bs[p][kb + r + 4][n0w + nt * 8 + q];
                bhi[nt][0] = tf32r(u0); blo[nt][0] = __float_as_uint(u0 - __uint_as_float(bhi[nt][0]));
                bhi[nt][1] = tf32r(u1); blo[nt][1] = __float_as_uint(u1 - __uint_as_float(bhi[nt][1]));
            }
            // 3xTF32: hi*hi + hi*lo + lo*hi
#pragma unroll
            for (int mt = 0; mt < 2; mt++)
#pragma unroll
                for (int nt = 0; nt < 4; nt++) {
                    mma8(acc[mt][nt], ahi[mt][0], ahi[mt][1], ahi[mt][2], ahi[mt][3],
                         bhi[nt][0], bhi[nt][1]);
                    mma8(acc[mt][nt], ahi[mt][0], ahi[mt][1], ahi[mt][2], ahi[mt][3],
                         blo[nt][0], blo[nt][1]);
                    mma8(acc[mt][nt], alo[mt][0], alo[mt][1], alo[mt][2], alo[mt][3],
                         bhi[nt][0], bhi[nt][1]);
                }
        }

        if (c + 1 < NC) sts((c + 1) & 1);
        __syncthreads();
    }

    // ---- epilogue: bias(+ReLU), float2 stores
#pragma unroll
    for (int mt = 0; mt < 2; mt++) {
        int row0 = m0 + m0w + mt * 16 + q;
        int row1 = row0 + 8;
        float bv0 = (row0 < Mtot) ? __ldg(bias + row0) : 0.f;
        float bv1 = (row1 < Mtot) ? __ldg(bias + row1) : 0.f;
#pragma unroll
        for (int nt = 0; nt < 4; nt++) {
            int cn = n0 + n0w + nt * 8 + 2 * r;
            float2 o0, o1;
            o0.x = acc[mt][nt][0] + bv0;
            o0.y = acc[mt][nt][1] + bv0;
            o1.x = acc[mt][nt][2] + bv1;
            o1.y = acc[mt][nt][3] + bv1;
            if (RELU) {
                o0.x = fmaxf(o0.x, 0.f); o0.y = fmaxf(o0.y, 0.f);
                o1.x = fmaxf(o1.x, 0.f); o1.y = fmaxf(o1.y, 0.f);
            }
            if (row0 < Mtot) *(float2*)&C[(size_t)row0 * N_ + cn] = o0;
            if (row1 < Mtot) *(float2*)&C[(size_t)row1 * N_ + cn] = o1;
        }
    }
}

// ---------------------------------------------------------------------------
// transpose: xT[n][ci] = x[ci][n]
// ---------------------------------------------------------------------------
__global__ void transpose_k(const float* __restrict__ x, float* __restrict__ xT)
{
    __shared__ float tl[32][33];
    int nb = blockIdx.x * 32, cb = blockIdx.y * 32;
    for (int j = threadIdx.y; j < 32; j += 8)
        tl[j][threadIdx.x] = x[(size_t)(cb + j) * N_ + nb + threadIdx.x];
    __syncthreads();
    for (int j = threadIdx.y; j < 32; j += 8)
        xT[(size_t)(nb + j) * CIN_ + cb + threadIdx.x] = tl[threadIdx.x][j];
}

// ---------------------------------------------------------------------------
// deform_col: col[(ci*27+k)][n] via trilinear interp; xT is [n][ci] so the
// 8 corner gathers are float4 loads along ci.
// ---------------------------------------------------------------------------
__global__ void deform_col_k(const float* __restrict__ xT,
                             const float* __restrict__ off,
                             float* __restrict__ col)
{
    int n = blockIdx.x * blockDim.x + threadIdx.x;
    if (n >= N_) return;
    int k = blockIdx.y;

    int t = n / (H_ * W_);
    int hw = n - t * (H_ * W_);
    int h = hw / W_;
    int w = hw - h * W_;

    int dt = k / 9 - 1, dh = (k / 3) % 3 - 1, dw = k % 3 - 1;

    float pt = (float)(t + dt) + off[(size_t)(k * 3 + 0) * N_ + n];
    float ph = (float)(h + dh) + off[(size_t)(k * 3 + 1) * N_ + n];
    float pw = (float)(w + dw) + off[(size_t)(k * 3 + 2) * N_ + n];

    float ft = floorf(pt), fh = floorf(ph), fw = floorf(pw);
    float at = pt - ft, ah = ph - fh, aw = pw - fw;
    int it = (int)ft, ih = (int)fh, iw = (int)fw;

    size_t idx8[8];
    float  wt8[8];
#pragma unroll
    for (int c = 0; c < 8; c++) {
        int ddt = (c >> 2) & 1, ddh = (c >> 1) & 1, ddw = c & 1;
        int tt = it + ddt, hh = ih + ddh, ww = iw + ddw;
        bool valid = (tt >= 0 && tt < T_ && hh >= 0 && hh < H_ && ww >= 0 && ww < W_);
        int tc = min(max(tt, 0), T_ - 1);
        int hc = min(max(hh, 0), H_ - 1);
        int wc = min(max(ww, 0), W_ - 1);
        float wg = (ddt ? at : 1.f - at) * (ddh ? ah : 1.f - ah) * (ddw ? aw : 1.f - aw);
        wt8[c]  = valid ? wg : 0.f;
        idx8[c] = (size_t)((tc * H_ + hc) * W_ + wc) * CIN_;
    }

    const size_t stride = (size_t)KV_ * N_;
    for (int c0 = 0; c0 < CIN_; c0 += 4) {
        float4 a4 = make_float4(0.f, 0.f, 0.f, 0.f);
#pragma unroll
        for (int c = 0; c < 8; c++) {
            float4 g = __ldg((const float4*)(xT + idx8[c] + c0));
            a4.x += wt8[c] * g.x;
            a4.y += wt8[c] * g.y;
            a4.z += wt8[c] * g.z;
            a4.w += wt8[c] * g.w;
        }
        size_t b = ((size_t)c0 * KV_ + k) * N_ + n;
        col[b]              = a4.x;
        col[b + stride]     = a4.y;
        col[b + 2 * stride] = a4.z;
        col[b + 3 * stride] = a4.w;
    }
}

// ---------------------------------------------------------------------------
extern "C" void kernel_launch(void* const* d_in, const int* in_sizes, int n_in,
                              void* d_out, int out_size)
{
    const float* x     = (const float*)d_in[0];
    const float* l1_w  = (const float*)d_in[1];
    const float* l1_b  = (const float*)d_in[2];
    const float* l2_w  = (const float*)d_in[3];
    const float* l2_b  = (const float*)d_in[4];
    const float* l3_w  = (const float*)d_in[5];
    const float* l3_b  = (const float*)d_in[6];
    const float* def_w = (const float*)d_in[7];
    const float* def_b = (const float*)d_in[8];
    const float* c3d_w = (const float*)d_in[9];
    const float* c3d_b = (const float*)d_in[10];
    float* out = (float*)d_out;

    float *col, *h1, *h2, *off, *xT;
    cudaGetSymbolAddress((void**)&col, g_col);
    cudaGetSymbolAddress((void**)&h1,  g_h1);
    cudaGetSymbolAddress((void**)&h2,  g_h2);
    cudaGetSymbolAddress((void**)&off, g_off);
    cudaGetSymbolAddress((void**)&xT,  g_xT);

    dim3 g256(N_ / BN, 2);   // M=256: two 128-row tiles
    dim3 g81 (N_ / BN, 1);   // M=81: one guarded tile

    gemm_mma<true,  true ><<<g256, 256>>>(l1_w, x,  l1_b, h1, 256);
    gemm_mma<true,  true ><<<g256, 256>>>(l2_w, h1, l2_b, h2, 256);
    gemm_mma<true,  true ><<<g256, 256>>>(l3_w, h2, l3_b, h1, 256);
    gemm_mma<false, true ><<<g81,  256>>>(def_w, h1, def_b, off, 81);

    transpose_k<<<dim3(N_ / 32, CIN_ / 32), dim3(32, 8)>>>(x, xT);
    deform_col_k<<<dim3(N_ / 128, KV_), 128>>>(xT, off, col);

    gemm_mma<false, false><<<g256, 256>>>(c3d_w, col, c3d_b, out, 256);
}